// round 9
// baseline (speedup 1.0000x reference)
#include <cuda_runtime.h>
#include <cstdint>

// Problem constants (fixed by the dataset)
#define DD 16
#define BB 8
#define EE 2048
#define OO 2048

#define ECH    8                 // e's per chunk
#define NCHUNK (EE / ECH)        // 256
#define NTHREADS 128
#define OTILE  (NTHREADS * 4)    // 512 o's per block
#define NOT    (OO / OTILE)      // 4

#define DEPTH  8                 // smem ring slots (power of 2)
#define PD     6                 // prefetch distance (slot skew 6 of 8)

#define CP_ASYNC16(dst_u32, src_ptr) \
    asm volatile("cp.async.cg.shared.global [%0], [%1], 16;" \
                 :: "r"(dst_u32), "l"(src_ptr) : "memory")
#define CP_COMMIT() asm volatile("cp.async.commit_group;" ::: "memory")
#define CP_WAIT(N)  asm volatile("cp.async.wait_group %0;" :: "n"(N) : "memory")

__global__ __launch_bounds__(256)
void zero_out(float* __restrict__ out) {
    out[blockIdx.x * 256 + threadIdx.x] = 0.0f;
}

__global__ __launch_bounds__(NTHREADS, 7)   // 148*7 = 1036 >= 1024 -> single wave
void delta_synapse_main(const float* __restrict__ W,
                        const float* __restrict__ signs,
                        const float* __restrict__ Xd,
                        const float* __restrict__ Wshort,
                        const float* __restrict__ dmap,
                        float* __restrict__ out) {
    __shared__ float    coef[DD * BB][ECH];        // 4 KB: Xd*(Wshort+1)
    __shared__ float4   weffs[ECH][NTHREADS];      // 8 KB: W*signs slice
    __shared__ float4   ring[DEPTH][NTHREADS];     // 16 KB: staged dmap rows
    // Packed worklist: low32 = element offset (d*EE+e)*OO, high32 = el|d<<3|bm<<7
    __shared__ uint64_t wl64[ECH * DD + DEPTH + 8];
    __shared__ int wl_n;
    __shared__ int wl_npad;

    const int tid   = threadIdx.x;
    const int chunk = blockIdx.x;                  // 0..255
    const int otile = blockIdx.y;                  // 0..3
    const int e0    = chunk * ECH;
    const int obase = otile * OTILE + tid * 4;

    if (tid == 0) wl_n = 0;
    __syncthreads();

    // ---- Phase 1: coef[d*8+b][el] = Xd * (Wshort + 1)  (1024 elems, 8/thread)
    #pragma unroll
    for (int r = 0; r < (DD * BB * ECH) / NTHREADS; r++) {
        const int idx = r * NTHREADS + tid;
        const int el  = idx & (ECH - 1);
        const int g   = idx >> 3;                   // d*8 + b
        const int gi  = g * EE + e0 + el;
        const float x = Xd[gi];
        coef[g][el] = x * (Wshort[gi] + 1.0f);
    }
    __syncthreads();

    // ---- Phase 2: one thread per (el,d) pair (8*16 = 128): bmask + packed entry
    {
        const int el = tid & (ECH - 1);
        const int d  = tid >> 3;                    // 0..15
        unsigned bm = 0;
        #pragma unroll
        for (int b = 0; b < BB; b++)
            if (coef[d * BB + b][el] != 0.0f) bm |= 1u << b;
        if (bm) {
            const int pos = atomicAdd(&wl_n, 1);
            const uint32_t off  = (uint32_t)(d * EE + e0 + el) * OO;
            const uint32_t meta = (uint32_t)(el | (d << 3) | (bm << 7));
            wl64[pos] = (uint64_t)off | ((uint64_t)meta << 32);
        }
    }

    // ---- Phase 3: Weff = W*signs into smem (independent loads → full MLP)
    #pragma unroll
    for (int el = 0; el < ECH; el++) {
        const size_t row = (size_t)(e0 + el) * OO + obase;
        const float4 wv = __ldcs((const float4*)&W[row]);
        const float4 sv = __ldcs((const float4*)&signs[row]);
        weffs[el][tid] =
            make_float4(wv.x * sv.x, wv.y * sv.y, wv.z * sv.z, wv.w * sv.w);
    }
    __syncthreads();                                // wl_n final, weffs visible

    // ---- Pad worklist with sentinels (offset 0, bm=0 → harmless no-op loads)
    if (tid == 0) {
        const int n = wl_n;
        for (int k = n; k < n + DEPTH + 8; k++) wl64[k] = 0ull;
        wl_npad = n;
    }
    __syncthreads();

    float4 acc[BB];
    #pragma unroll
    for (int b = 0; b < BB; b++) acc[b] = make_float4(0.f, 0.f, 0.f, 0.f);

    // ---- Phase 4: cp.async smem-ring pipeline over the worklist.
    //      Pipeline depth lives in SMEM, not registers.
    const float* dbase = dmap + obase;
    const uint2* wl32  = (const uint2*)wl64;        // .x = offset, .y = meta
    uint32_t ring_u32;
    {
        uint32_t r32;
        asm("{ .reg .u64 t; cvta.to.shared.u64 t, %1; cvt.u32.u64 %0, t; }"
            : "=r"(r32) : "l"(&ring[0][tid]));
        ring_u32 = r32;                             // this thread's lane in slot 0
    }
    const int n = wl_npad;

    // Prologue: issue entries 0..PD-1 into slots 0..PD-1 (one group each)
    #pragma unroll
    for (int j = 0; j < PD; j++) {
        const uint2 w = wl32[j];
        CP_ASYNC16(ring_u32 + j * (NTHREADS * 16), dbase + w.x);
        CP_COMMIT();
    }

    int islot = PD;                                 // slot for entry k+PD
    int cslot = 0;                                  // slot for entry k
    #pragma unroll 2
    for (int k = 0; k < n; k++) {
        // issue entry k+PD (sentinel-padded, always valid)
        const uint2 wn = wl32[k + PD];
        CP_ASYNC16(ring_u32 + islot * (NTHREADS * 16), dbase + wn.x);
        CP_COMMIT();
        if (++islot == DEPTH) islot = 0;

        CP_WAIT(PD);                                // entry k's row is in smem
        const float4 dm = ring[cslot][tid];
        if (++cslot == DEPTH) cslot = 0;

        const uint32_t meta = wl32[k].y;            // smem broadcast
        const int el = meta & 7;
        const int d  = (meta >> 3) & 15;
        unsigned bm  = meta >> 7;

        const float4 wv = weffs[el][tid];
        const float t0 = wv.x * dm.x;
        const float t1 = wv.y * dm.y;
        const float t2 = wv.z * dm.z;
        const float t3 = wv.w * dm.w;
        const float* crow = &coef[d * BB][el];      // +b*ECH per batch
        while (bm) {                                // avg ~1.2 active batches
            const int b = __ffs(bm) - 1;
            bm &= bm - 1;
            const float c = crow[b * ECH];          // smem broadcast
            switch (b) {                            // static acc indexing
            case 0: acc[0].x += t0*c; acc[0].y += t1*c; acc[0].z += t2*c; acc[0].w += t3*c; break;
            case 1: acc[1].x += t0*c; acc[1].y += t1*c; acc[1].z += t2*c; acc[1].w += t3*c; break;
            case 2: acc[2].x += t0*c; acc[2].y += t1*c; acc[2].z += t2*c; acc[2].w += t3*c; break;
            case 3: acc[3].x += t0*c; acc[3].y += t1*c; acc[3].z += t2*c; acc[3].w += t3*c; break;
            case 4: acc[4].x += t0*c; acc[4].y += t1*c; acc[4].z += t2*c; acc[4].w += t3*c; break;
            case 5: acc[5].x += t0*c; acc[5].y += t1*c; acc[5].z += t2*c; acc[5].w += t3*c; break;
            case 6: acc[6].x += t0*c; acc[6].y += t1*c; acc[6].z += t2*c; acc[6].w += t3*c; break;
            default: acc[7].x += t0*c; acc[7].y += t1*c; acc[7].z += t2*c; acc[7].w += t3*c; break;
            }
        }
    }

    // ---- Phase 5: reduce directly into out via vector REDG (no return value).
    //      Per address only NCHUNK=256 adds over the whole kernel -> no contention.
    #pragma unroll
    for (int b = 0; b < BB; b++) {
        float* dst = out + b * OO + obase;
        asm volatile("red.global.add.v4.f32 [%0], {%1, %2, %3, %4};"
                     :: "l"(dst),
                        "f"(acc[b].x), "f"(acc[b].y), "f"(acc[b].z), "f"(acc[b].w)
                     : "memory");
    }
}

extern "C" void kernel_launch(void* const* d_in, const int* in_sizes, int n_in,
                              void* d_out, int out_size) {
    (void)in_sizes; (void)n_in; (void)out_size;
    const float* W      = (const float*)d_in[0];
    const float* signs  = (const float*)d_in[1];
    const float* Xd     = (const float*)d_in[2];
    const float* Wshort = (const float*)d_in[3];
    const float* dmap   = (const float*)d_in[4];
    float* out = (float*)d_out;

    zero_out<<<(BB * OO) / 256, 256>>>(out);
    dim3 grid(NCHUNK, NOT);                       // 256 x 4 = 1024 blocks, 1 wave
    delta_synapse_main<<<grid, NTHREADS>>>(W, signs, Xd, Wshort, dmap, out);
}

// round 10
// speedup vs baseline: 1.2979x; 1.2979x over previous
#include <cuda_runtime.h>
#include <cstdint>

// Problem constants (fixed by the dataset)
#define DD 16
#define BB 8
#define EE 2048
#define OO 2048

#define ECH    8                 // e's per chunk
#define NCHUNK (EE / ECH)        // 256
#define NTHREADS 128
#define OTILE  (NTHREADS * 4)    // 512 o's per block
#define NOT    (OO / OTILE)      // 4
#define PF     4                 // prefetch pipeline depth (regs: buf only)

__global__ __launch_bounds__(256)
void zero_out(float* __restrict__ out) {
    out[blockIdx.x * 256 + threadIdx.x] = 0.0f;
}

__global__ __launch_bounds__(NTHREADS, 7)   // 148*7 = 1036 >= 1024 -> single wave
void delta_synapse_main(const float* __restrict__ W,
                        const float* __restrict__ signs,
                        const float* __restrict__ Xd,
                        const float* __restrict__ Wshort,
                        const float* __restrict__ dmap,
                        float* __restrict__ out) {
    __shared__ float    coef[DD * BB][ECH];        // 4 KB: Xd*(Wshort+1)
    __shared__ float4   weffs[ECH][NTHREADS];      // 8 KB: W*signs slice
    // Split worklist: offsets consumed at issue time, meta at consume time.
    __shared__ uint32_t wl_off [ECH * DD + 2 * PF];  // (d*EE+e)*OO element offset
    __shared__ uint32_t wl_meta[ECH * DD + 2 * PF];  // el | d<<3 | bm<<7
    __shared__ int wl_n;
    __shared__ int wl_npad;

    const int tid   = threadIdx.x;
    const int chunk = blockIdx.x;                  // 0..255
    const int otile = blockIdx.y;                  // 0..3
    const int e0    = chunk * ECH;
    const int obase = otile * OTILE + tid * 4;

    if (tid == 0) wl_n = 0;
    __syncthreads();

    // ---- Phase 1: coef[d*8+b][el] = Xd * (Wshort + 1)  (1024 elems, 8/thread)
    #pragma unroll
    for (int r = 0; r < (DD * BB * ECH) / NTHREADS; r++) {
        const int idx = r * NTHREADS + tid;
        const int el  = idx & (ECH - 1);
        const int g   = idx >> 3;                   // d*8 + b
        const int gi  = g * EE + e0 + el;
        const float x = Xd[gi];
        coef[g][el] = x * (Wshort[gi] + 1.0f);
    }
    __syncthreads();

    // ---- Phase 2: one thread per (el,d) pair (8*16 = 128): bmask + entry
    {
        const int el = tid & (ECH - 1);
        const int d  = tid >> 3;                    // 0..15
        unsigned bm = 0;
        #pragma unroll
        for (int b = 0; b < BB; b++)
            if (coef[d * BB + b][el] != 0.0f) bm |= 1u << b;
        if (bm) {
            const int pos = atomicAdd(&wl_n, 1);
            wl_off [pos] = (uint32_t)(d * EE + e0 + el) * OO;
            wl_meta[pos] = (uint32_t)(el | (d << 3) | (bm << 7));
        }
    }

    // ---- Phase 3: Weff = W*signs into smem (independent loads → full MLP)
    #pragma unroll
    for (int el = 0; el < ECH; el++) {
        const size_t row = (size_t)(e0 + el) * OO + obase;
        const float4 wv = __ldcs((const float4*)&W[row]);
        const float4 sv = __ldcs((const float4*)&signs[row]);
        weffs[el][tid] =
            make_float4(wv.x * sv.x, wv.y * sv.y, wv.z * sv.z, wv.w * sv.w);
    }
    __syncthreads();                                // wl_n final, weffs visible

    // ---- Pad worklist to PF multiple + PF sentinels (off=0, bm=0 → no-ops)
    if (tid == 0) {
        const int n    = wl_n;
        const int npad = (n + PF - 1) & ~(PF - 1);
        for (int k = n; k < npad + PF; k++) { wl_off[k] = 0u; wl_meta[k] = 0u; }
        wl_npad = npad;
    }
    __syncthreads();

    float4 acc[BB];
    #pragma unroll
    for (int b = 0; b < BB; b++) acc[b] = make_float4(0.f, 0.f, 0.f, 0.f);

    // ---- Phase 4: PF-deep LDG pipeline; only buf[] lives in registers.
    const float* dbase = dmap + obase;
    const int npad = wl_npad;
    float4 buf[PF];
    #pragma unroll
    for (int j = 0; j < PF; j++)
        buf[j] = __ldcs((const float4*)(dbase + wl_off[j]));

    for (int i = 0; i < npad; i += PF) {
        #pragma unroll
        for (int j = 0; j < PF; j++) {
            const int k = i + j;
            const float4 dm = buf[j];

            // issue entry k+PF (sentinel-padded, always in-bounds)
            buf[j] = __ldcs((const float4*)(dbase + wl_off[k + PF]));

            const uint32_t meta = wl_meta[k];       // smem broadcast (hoistable)
            unsigned bm = meta >> 7;
            if (bm) {                               // warp-uniform
                const int el = meta & 7;
                const int d  = (meta >> 3) & 15;
                const float4 wv = weffs[el][tid];
                const float t0 = wv.x * dm.x;
                const float t1 = wv.y * dm.y;
                const float t2 = wv.z * dm.z;
                const float t3 = wv.w * dm.w;
                const float* crow = &coef[d * BB][el];  // +b*ECH per batch
                while (bm) {                        // avg ~1.2 active batches
                    const int b = __ffs(bm) - 1;
                    bm &= bm - 1;
                    const float c = crow[b * ECH];  // smem broadcast
                    switch (b) {                    // static acc indexing
                    case 0: acc[0].x += t0*c; acc[0].y += t1*c; acc[0].z += t2*c; acc[0].w += t3*c; break;
                    case 1: acc[1].x += t0*c; acc[1].y += t1*c; acc[1].z += t2*c; acc[1].w += t3*c; break;
                    case 2: acc[2].x += t0*c; acc[2].y += t1*c; acc[2].z += t2*c; acc[2].w += t3*c; break;
                    case 3: acc[3].x += t0*c; acc[3].y += t1*c; acc[3].z += t2*c; acc[3].w += t3*c; break;
                    case 4: acc[4].x += t0*c; acc[4].y += t1*c; acc[4].z += t2*c; acc[4].w += t3*c; break;
                    case 5: acc[5].x += t0*c; acc[5].y += t1*c; acc[5].z += t2*c; acc[5].w += t3*c; break;
                    case 6: acc[6].x += t0*c; acc[6].y += t1*c; acc[6].z += t2*c; acc[6].w += t3*c; break;
                    default: acc[7].x += t0*c; acc[7].y += t1*c; acc[7].z += t2*c; acc[7].w += t3*c; break;
                    }
                }
            }
        }
    }

    // ---- Phase 5: reduce directly into out via vector REDG (no return value).
    //      Per address only NCHUNK=256 adds over the whole kernel -> no contention.
    #pragma unroll
    for (int b = 0; b < BB; b++) {
        float* dst = out + b * OO + obase;
        asm volatile("red.global.add.v4.f32 [%0], {%1, %2, %3, %4};"
                     :: "l"(dst),
                        "f"(acc[b].x), "f"(acc[b].y), "f"(acc[b].z), "f"(acc[b].w)
                     : "memory");
    }
}

extern "C" void kernel_launch(void* const* d_in, const int* in_sizes, int n_in,
                              void* d_out, int out_size) {
    (void)in_sizes; (void)n_in; (void)out_size;
    const float* W      = (const float*)d_in[0];
    const float* signs  = (const float*)d_in[1];
    const float* Xd     = (const float*)d_in[2];
    const float* Wshort = (const float*)d_in[3];
    const float* dmap   = (const float*)d_in[4];
    float* out = (float*)d_out;

    zero_out<<<(BB * OO) / 256, 256>>>(out);
    dim3 grid(NCHUNK, NOT);                       // 256 x 4 = 1024 blocks, 1 wave
    delta_synapse_main<<<grid, NTHREADS>>>(W, signs, Xd, Wshort, dmap, out);
}